// round 1
// baseline (speedup 1.0000x reference)
#include <cuda_runtime.h>

#define NPIX   289
#define STEPS  512
#define PP     20           // padded tile pitch (19 rows used)
#define TILE   384          // 19*20 = 380, padded
#define NT     320          // threads per block (10 warps)
#define HBS    290          // hbias row stride (ull) per op-pair

typedef unsigned long long u64;
typedef unsigned int u32;

__device__ __forceinline__ u64 ffma2(u64 a, u64 b, u64 c){
    u64 d; asm("fma.rn.f32x2 %0, %1, %2, %3;" : "=l"(d) : "l"(a), "l"(b), "l"(c)); return d;
}
__device__ __forceinline__ u64 pack2(float x, float y){
    u64 r; asm("mov.b64 %0, {%1, %2};" : "=l"(r)
               : "r"(__float_as_uint(x)), "r"(__float_as_uint(y)));
    return r;
}
__device__ __forceinline__ void unpack2(u64 v, float &x, float &y){
    u32 a, b; asm("mov.b64 {%0, %1}, %2;" : "=r"(a), "=r"(b) : "l"(v));
    x = __uint_as_float(a); y = __uint_as_float(b);
}

#define SMEM_U64  (448 + 32*HBS)          /* w1I(320) + f2I(128) + hbias(32*290) */
#define SMEM_F    (5*TILE + 4 + 12)       /* 5 tiles + b2(4) + wsum(10,padded)   */
#define SMEM_BYTES (SMEM_U64*8 + SMEM_F*4)

__global__ void __launch_bounds__(NT, 1) ca_kernel(
    const float* __restrict__ cell, const float* __restrict__ food,
    const float* __restrict__ fc1w, const float* __restrict__ fc1b,
    const float* __restrict__ fc2w, const float* __restrict__ fc2b,
    float* __restrict__ out)
{
    extern __shared__ u64 sm[];
    u64*   w1I = sm;            // [32][10] (o-pair, j) ; j=9 is zero pad
    u64*   f2I = sm + 320;      // [32][4]  (o-pair, o2)
    u64*   hb2 = sm + 448;      // [32][HBS] hbias pairs, [op][pixel]
    float* fb  = (float*)(sm + SMEM_U64);
    float* sc0 = fb;            // padded cell ch0 tile
    float* sc1 = fb + TILE;
    float* sc2 = fb + 2*TILE;
    float* x0t = fb + 3*TILE;   // padded x0 tile for post-maxpool
    float* sct = fb + 4*TILE;   // padded scent tile
    float* b2s  = fb + 5*TILE;  // 4
    float* wsum = b2s + 4;      // 10

    const int  tid = threadIdx.x;
    const int  b   = blockIdx.x;
    const bool act = tid < NPIX;
    const int  r   = tid / 17, cc = tid % 17;
    const int  idx = (r + 1) * PP + (cc + 1);

    // ---- init: zero tiles (halo stays zero forever) ----
    for (int i = tid; i < TILE; i += NT){
        sc0[i]=0.f; sc1[i]=0.f; sc2[i]=0.f; x0t[i]=0.f; sct[i]=0.f;
    }

    // ---- weight interleave ----
    {
        const int cjmap[9] = {0,1,2,4,5,6,8,9,10};   // varying y indices
        int op = tid / 10, j = tid % 10;             // tid in [0,320)
        float wa = 0.f, wb = 0.f;
        if (j < 9){
            wa = fc1w[(2*op)   * 12 + cjmap[j]];
            wb = fc1w[(2*op+1) * 12 + cjmap[j]];
        }
        w1I[tid] = pack2(wa, wb);
        if (tid < 128){
            int o = tid >> 2, o2 = tid & 3;
            f2I[tid] = pack2(fc2w[o2*64 + 2*o], fc2w[o2*64 + 2*o + 1]);
        }
        if (tid < 4) b2s[tid] = fc2b[tid];
    }
    __syncthreads();

    // ---- load cell, compute scent (constant across steps) ----
    float c0v = 0.f, scv = 0.f;
    if (act){
        c0v = cell[(b*4 + 0)*NPIX + tid];
        sc0[idx] = c0v;
        sc1[idx] = cell[(b*4 + 1)*NPIX + tid];
        sc2[idx] = cell[(b*4 + 2)*NPIX + tid];
        const float SW[5][5] = {
            {0.f,   0.125f,0.25f,0.125f,0.f  },
            {0.125f,0.25f, 0.5f, 0.25f, 0.125f},
            {0.25f, 0.5f,  1.0f, 0.5f,  0.25f },
            {0.125f,0.25f, 0.5f, 0.25f, 0.125f},
            {0.f,   0.125f,0.25f,0.125f,0.f  }};
        float s = 0.f;
        #pragma unroll
        for (int di = 0; di < 5; di++)
            #pragma unroll
            for (int dj = 0; dj < 5; dj++){
                int rr = r + di - 2, c2 = cc + dj - 2;
                if (rr >= 0 && rr < 17 && c2 >= 0 && c2 < 17)
                    s += SW[di][dj] * food[b*NPIX + rr*17 + c2];
            }
        scv = s;
        sct[idx] = s;
    }
    int living = __syncthreads_count(act && (c0v > 0.1f));   // also a barrier

    // ---- hbias: fold b1 + w1[:,3]*scent + w1[:,7]*dx(scent) + w1[:,11]*dy(scent) ----
    if (act){
        float m00=sct[idx-PP-1], m01=sct[idx-PP], m02=sct[idx-PP+1];
        float m10=sct[idx-1],                     m12=sct[idx+1];
        float m20=sct[idx+PP-1], m21=sct[idx+PP], m22=sct[idx+PP+1];
        float dsx = (m02 - m00 + 2.f*(m12 - m10) + m22 - m20) * 0.125f;
        float dsy = (m20 - m00 + 2.f*(m21 - m01) + m22 - m02) * 0.125f;
        #pragma unroll 4
        for (int op = 0; op < 32; op++){
            float h0 = fc1b[2*op]   + fc1w[(2*op)*12+3]  *scv
                     + fc1w[(2*op)*12+7]  *dsx + fc1w[(2*op)*12+11]  *dsy;
            float h1 = fc1b[2*op+1] + fc1w[(2*op+1)*12+3]*scv
                     + fc1w[(2*op+1)*12+7]*dsx + fc1w[(2*op+1)*12+11]*dsy;
            hb2[op*HBS + tid] = pack2(h0, h1);
        }
    }
    __syncthreads();

    // ---- main 512-step loop ----
    float c0f = 0.f, c1n = 0.f, c2n = 0.f, c3n = 0.f;

    for (int s = 0; s < STEPS; s++){
        float x0 = 0.f, x1 = 0.f, x2 = 0.f, x3 = 0.f;
        bool  pre = false;

        if (act){
            // channel 0: neighborhood -> premask + value + sobel
            float a00=sc0[idx-PP-1], a01=sc0[idx-PP], a02=sc0[idx-PP+1];
            float a10=sc0[idx-1],    a11=sc0[idx],    a12=sc0[idx+1];
            float a20=sc0[idx+PP-1], a21=sc0[idx+PP], a22=sc0[idx+PP+1];
            float mx = fmaxf(fmaxf(fmaxf(a00,a01), fmaxf(a02,a10)),
                             fmaxf(fmaxf(a11,a12), fmaxf(fmaxf(a20,a21), a22)));
            pre = mx > 0.1f;
            float y0 = a11;
            float y3 = (a02 - a00 + 2.f*(a12 - a10) + a22 - a20) * 0.125f;
            float y6 = (a20 - a00 + 2.f*(a21 - a01) + a22 - a02) * 0.125f;

            float b00=sc1[idx-PP-1], b01=sc1[idx-PP], b02=sc1[idx-PP+1];
            float b10=sc1[idx-1],    b11=sc1[idx],    b12=sc1[idx+1];
            float b20=sc1[idx+PP-1], b21=sc1[idx+PP], b22=sc1[idx+PP+1];
            float y1 = b11;
            float y4 = (b02 - b00 + 2.f*(b12 - b10) + b22 - b20) * 0.125f;
            float y7 = (b20 - b00 + 2.f*(b21 - b01) + b22 - b02) * 0.125f;

            float e00=sc2[idx-PP-1], e01=sc2[idx-PP], e02=sc2[idx-PP+1];
            float e10=sc2[idx-1],    e11=sc2[idx],    e12=sc2[idx+1];
            float e20=sc2[idx+PP-1], e21=sc2[idx+PP], e22=sc2[idx+PP+1];
            float y2 = e11;
            float y5 = (e02 - e00 + 2.f*(e12 - e10) + e22 - e20) * 0.125f;
            float y8 = (e20 - e00 + 2.f*(e21 - e01) + e22 - e02) * 0.125f;

            u64 Y0=pack2(y0,y0), Y1=pack2(y1,y1), Y2=pack2(y2,y2);
            u64 Y3=pack2(y3,y3), Y4=pack2(y4,y4), Y5=pack2(y5,y5);
            u64 Y6=pack2(y6,y6), Y7=pack2(y7,y7), Y8=pack2(y8,y8);

            // MLP: 32 hidden pairs, packed f32x2 FMAs
            u64 d0 = 0ull, d1 = 0ull, d2 = 0ull, d3 = 0ull;
            #pragma unroll
            for (int op = 0; op < 32; op++){
                u64 acc = hb2[op*HBS + tid];
                const ulonglong2* wr = reinterpret_cast<const ulonglong2*>(w1I + op*10);
                ulonglong2 wA = wr[0], wB = wr[1], wC = wr[2], wD = wr[3], wE = wr[4];
                acc = ffma2(wA.x, Y0, acc);
                acc = ffma2(wA.y, Y1, acc);
                acc = ffma2(wB.x, Y2, acc);
                acc = ffma2(wB.y, Y3, acc);
                acc = ffma2(wC.x, Y4, acc);
                acc = ffma2(wC.y, Y5, acc);
                acc = ffma2(wD.x, Y6, acc);
                acc = ffma2(wD.y, Y7, acc);
                acc = ffma2(wE.x, Y8, acc);
                float lo, hi; unpack2(acc, lo, hi);
                lo = fmaxf(lo, 0.f); hi = fmaxf(hi, 0.f);          // relu
                acc = pack2(lo, hi);
                const ulonglong2* fr = reinterpret_cast<const ulonglong2*>(f2I + op*4);
                ulonglong2 fA = fr[0], fB = fr[1];
                d0 = ffma2(fA.x, acc, d0);
                d1 = ffma2(fA.y, acc, d1);
                d2 = ffma2(fB.x, acc, d2);
                d3 = ffma2(fB.y, acc, d3);
            }
            float l0,h0; unpack2(d0,l0,h0); float dl0 = l0 + h0 + b2s[0];
            float l1,h1; unpack2(d1,l1,h1); float dl1 = l1 + h1 + b2s[1];
            float l2,h2; unpack2(d2,l2,h2); float dl2 = l2 + h2 + b2s[2];
            float l3,h3; unpack2(d3,l3,h3); float dl3 = l3 + h3 + b2s[3];

            x0 = y0 + dl0; x1 = y1 + dl1; x2 = y2 + dl2; x3 = scv + dl3;
            x0t[idx] = x0;
        }
        __syncthreads();

        u32 bits = 0; float c0p = 0.f;
        if (act){
            float p00=x0t[idx-PP-1], p01=x0t[idx-PP], p02=x0t[idx-PP+1];
            float p10=x0t[idx-1],    p11=x0,          p12=x0t[idx+1];
            float p20=x0t[idx+PP-1], p21=x0t[idx+PP], p22=x0t[idx+PP+1];
            float pm = fmaxf(fmaxf(fmaxf(p00,p01), fmaxf(p02,p10)),
                             fmaxf(fmaxf(p11,p12), fmaxf(fmaxf(p20,p21), p22)));
            bool m = pre && (pm > 0.1f);
            // x*mask then clip == (m ? clip : 0)
            c0p = m ? fminf(fmaxf(x0,   0.f),  1.f) : 0.f;
            c1n = m ? fminf(fmaxf(x1, -10.f), 10.f) : 0.f;
            c2n = m ? fminf(fmaxf(x2, -10.f), 10.f) : 0.f;
            c3n = m ? fminf(fmaxf(x3, -10.f), 10.f) : 0.f;
            sc1[idx] = c1n; sc2[idx] = c2n;
            bits = __float_as_uint(c0p);          // c0p in [0,1] -> monotone bits
        }

        // exact kth-largest via radix bit-descent (values <= 1.0f = 0x3F800000)
        int kk = living - 1; if (kk < 0) kk += NPIX;   // torch negative-index wrap
        const int need = kk + 1;
        u32 prefix = 0;
        #pragma unroll 1
        for (int bit = 29; bit >= 0; bit--){
            u32 trial = prefix | (1u << bit);
            int cnt = __syncthreads_count(act && (bits >= trial));
            if (cnt >= need) prefix = trial;
        }
        c0f = (act && bits >= prefix) ? c0p : 0.f;
        if (act) sc0[idx] = c0f;
        living = __syncthreads_count(act && (c0f > 0.1f));  // barrier orders sc0 writes
    }

    // ---- outputs: [cell(16,4,289) | food(16,289) | total(16) | living(16)] ----
    if (act){
        int cb = (b*4)*NPIX + tid;
        out[cb]           = c0f;
        out[cb +   NPIX]  = c1n;
        out[cb + 2*NPIX]  = c2n;
        out[cb + 3*NPIX]  = c3n;
        out[16*4*NPIX + b*NPIX + tid] = food[b*NPIX + tid];
    }
    float v = act ? c0f : 0.f;
    #pragma unroll
    for (int off = 16; off; off >>= 1) v += __shfl_down_sync(0xffffffffu, v, off);
    if ((tid & 31) == 0) wsum[tid >> 5] = v;
    __syncthreads();
    if (tid == 0){
        float t = 0.f;
        #pragma unroll
        for (int i = 0; i < 10; i++) t += wsum[i];
        out[23120 + b]      = t;               // total_pixel_val
        out[23120 + 16 + b] = (float)living;   // living_count
    }
}

extern "C" void kernel_launch(void* const* d_in, const int* in_sizes, int n_in,
                              void* d_out, int out_size)
{
    const float* cell = (const float*)d_in[0];
    const float* food = (const float*)d_in[1];
    // d_in[2] = steps (fixed at 512 for this problem)
    const float* fc1w = (const float*)d_in[3];
    const float* fc1b = (const float*)d_in[4];
    const float* fc2w = (const float*)d_in[5];
    const float* fc2b = (const float*)d_in[6];
    float* out = (float*)d_out;

    cudaFuncSetAttribute(ca_kernel, cudaFuncAttributeMaxDynamicSharedMemorySize, SMEM_BYTES);
    ca_kernel<<<16, NT, SMEM_BYTES>>>(cell, food, fc1w, fc1b, fc2w, fc2b, out);
}